// round 14
// baseline (speedup 1.0000x reference)
#include <cuda_runtime.h>
#include <cuda_bf16.h>
#include <math.h>

// Problem constants
#define Bsz 4096
#define Ssz 1536
#define Lsz 2048
#define Hsz 1024
#define MINTOK 460                     // int(0.3*1536)
#define NEEDFIX_THRESH (Ssz - MINTOK)  // 1076

// ---------------- scratch (device globals; no allocations allowed) ----------
__device__ float g_A [(size_t)Bsz * Lsz];
__device__ float g_Bf[(size_t)Bsz * Lsz];
__device__ float g_C1[(size_t)Bsz * Hsz];
__device__ float g_C2[(size_t)Bsz * Hsz];
__device__ float g_C3[(size_t)Bsz * Hsz];
__device__ float g_D1[(size_t)Bsz * (Hsz/2)];
__device__ float g_D2[(size_t)Bsz * (Hsz/4)];

#define CCH 64
__device__ double g_p1[CCH * Lsz];
__device__ double g_p2[CCH * Lsz];
__device__ double g_p3[CCH * Lsz];
__device__ double g_S1[Lsz], g_S2[Lsz], g_S3[Lsz];
__device__ float  g_adj[Lsz];
__device__ float  g_rowEnt[Bsz], g_rowDiff[Bsz];
__device__ double g_cons[1];

// ---- f32x2 packed helpers (PTX-only; each half is an independent IEEE op) --
__device__ __forceinline__ unsigned long long pk2(float lo, float hi) {
    unsigned long long r;
    asm("mov.b64 %0, {%1, %2};" : "=l"(r) : "f"(lo), "f"(hi));
    return r;
}
__device__ __forceinline__ void upk2(unsigned long long v, float& lo, float& hi) {
    asm("mov.b64 {%0, %1}, %2;" : "=f"(lo), "=f"(hi) : "l"(v));
}
__device__ __forceinline__ unsigned long long fma2(unsigned long long a,
                                                   unsigned long long b,
                                                   unsigned long long c) {
    unsigned long long d;
    asm("fma.rn.f32x2 %0, %1, %2, %3;" : "=l"(d) : "l"(a), "l"(b), "l"(c));
    return d;
}

union F4U2 { float4 f; struct { unsigned long long lo, hi; } u; };

__device__ __forceinline__ double warp_rsum_d(double x) {
#pragma unroll
    for (int o = 16; o > 0; o >>= 1)
        x += __shfl_down_sync(0xffffffffu, x, o);
    return x;
}

// ---------------- GEMM: C[M,N] = A[M,K] @ W[N,K]^T + bias[N] ----------------
// Numerics (frozen, = round 13): per output, fp32 FFMA over each ascending
// 64-k chunk; chunk sums folded ascending into an fp32 accumulator;
// (ksum)+bias at the end. f32x2 packs two M-adjacent outputs per instruction.
// SIGMOID==1 additionally applies clip(-5,5) + exact double sigmoid to the
// epilogue value (identical op sequence to the old standalone kernel).
// Perf: 128x64 tile, 8x4/thread, 256 threads, BK=16 double-buffered stages,
// ONE __syncthreads per stage (the pre-staging barrier was redundant:
// stores target the buffer nobody reads until after the remaining barrier).
template<int SIGMOID>
__global__ void __launch_bounds__(256, 2)
sgemm_nt(const float* __restrict__ A, const float* __restrict__ W,
         const float* __restrict__ bias, float* __restrict__ C,
         int M, int N, int K)
{
    constexpr int BK = 16;
    __shared__ float As[2][BK][128];
    __shared__ float Bs[2][BK][64 + 4];
    const int tid = threadIdx.x;
    const int bm = blockIdx.y * 128;
    const int bn = blockIdx.x * 64;
    const int tr = (tid >> 4) << 3;     // 0..120 step 8
    const int tc = (tid & 15) << 2;     // 0..60 step 4

    const int arow = tid & 127;
    const int ak   = (tid >> 7) << 3;   // 0 or 8
    const int brow = tid & 63;
    const int bk   = (tid >> 6) << 2;   // 0,4,8,12

    const float* Ap = A + (size_t)(bm + arow) * K + ak;
    const float* Wp = W + (size_t)(bn + brow) * K + bk;

    unsigned long long facc2[4][4];
    float ksum[8][4];
#pragma unroll
    for (int i = 0; i < 8; i++)
#pragma unroll
        for (int j = 0; j < 4; j++) ksum[i][j] = 0.f;
#pragma unroll
    for (int p = 0; p < 4; p++)
#pragma unroll
        for (int j = 0; j < 4; j++) facc2[p][j] = 0ull;

    const int nch = K / BK;   // 16-k stages; fold every 4 stages (64 k)

    float4 aq0 = *(const float4*)(Ap);
    float4 aq1 = *(const float4*)(Ap + 4);
    float4 bq0 = *(const float4*)(Wp);
    As[0][ak + 0][arow] = aq0.x; As[0][ak + 1][arow] = aq0.y;
    As[0][ak + 2][arow] = aq0.z; As[0][ak + 3][arow] = aq0.w;
    As[0][ak + 4][arow] = aq1.x; As[0][ak + 5][arow] = aq1.y;
    As[0][ak + 6][arow] = aq1.z; As[0][ak + 7][arow] = aq1.w;
    Bs[0][bk + 0][brow] = bq0.x; Bs[0][bk + 1][brow] = bq0.y;
    Bs[0][bk + 2][brow] = bq0.z; Bs[0][bk + 3][brow] = bq0.w;
    __syncthreads();

    for (int c = 0; c < nch; c++) {
        const int buf = c & 1;
        const bool more = (c + 1 < nch);
        if (more) {
            const int k0 = (c + 1) * BK;
            aq0 = *(const float4*)(Ap + k0);
            aq1 = *(const float4*)(Ap + k0 + 4);
            bq0 = *(const float4*)(Wp + k0);
        }

#pragma unroll
        for (int k = 0; k < BK; k++) {
            F4U2 a0, a1;
            a0.f = *(const float4*)(&As[buf][k][tr]);
            a1.f = *(const float4*)(&As[buf][k][tr + 4]);
            const float4 bv = *(const float4*)(&Bs[buf][k][tc]);
            const unsigned long long bb0 = pk2(bv.x, bv.x);
            const unsigned long long bb1 = pk2(bv.y, bv.y);
            const unsigned long long bb2 = pk2(bv.z, bv.z);
            const unsigned long long bb3 = pk2(bv.w, bv.w);
            facc2[0][0] = fma2(a0.u.lo, bb0, facc2[0][0]);
            facc2[0][1] = fma2(a0.u.lo, bb1, facc2[0][1]);
            facc2[0][2] = fma2(a0.u.lo, bb2, facc2[0][2]);
            facc2[0][3] = fma2(a0.u.lo, bb3, facc2[0][3]);
            facc2[1][0] = fma2(a0.u.hi, bb0, facc2[1][0]);
            facc2[1][1] = fma2(a0.u.hi, bb1, facc2[1][1]);
            facc2[1][2] = fma2(a0.u.hi, bb2, facc2[1][2]);
            facc2[1][3] = fma2(a0.u.hi, bb3, facc2[1][3]);
            facc2[2][0] = fma2(a1.u.lo, bb0, facc2[2][0]);
            facc2[2][1] = fma2(a1.u.lo, bb1, facc2[2][1]);
            facc2[2][2] = fma2(a1.u.lo, bb2, facc2[2][2]);
            facc2[2][3] = fma2(a1.u.lo, bb3, facc2[2][3]);
            facc2[3][0] = fma2(a1.u.hi, bb0, facc2[3][0]);
            facc2[3][1] = fma2(a1.u.hi, bb1, facc2[3][1]);
            facc2[3][2] = fma2(a1.u.hi, bb2, facc2[3][2]);
            facc2[3][3] = fma2(a1.u.hi, bb3, facc2[3][3]);
        }

        if ((c & 3) == 3) {
            // plain fp32 fold of the completed 64-k chunk (ascending chunks)
#pragma unroll
            for (int p = 0; p < 4; p++)
#pragma unroll
                for (int j = 0; j < 4; j++) {
                    float flo, fhi;
                    upk2(facc2[p][j], flo, fhi);
                    ksum[2 * p][j]     = __fadd_rn(ksum[2 * p][j], flo);
                    ksum[2 * p + 1][j] = __fadd_rn(ksum[2 * p + 1][j], fhi);
                    facc2[p][j] = 0ull;
                }
        }

        if (more) {
            // single barrier per stage: stores below target buffer nb, which
            // is only read after the barrier; reads of buf all precede it.
            const int nb = buf ^ 1;
            As[nb][ak + 0][arow] = aq0.x; As[nb][ak + 1][arow] = aq0.y;
            As[nb][ak + 2][arow] = aq0.z; As[nb][ak + 3][arow] = aq0.w;
            As[nb][ak + 4][arow] = aq1.x; As[nb][ak + 5][arow] = aq1.y;
            As[nb][ak + 6][arow] = aq1.z; As[nb][ak + 7][arow] = aq1.w;
            Bs[nb][bk + 0][brow] = bq0.x; Bs[nb][bk + 1][brow] = bq0.y;
            Bs[nb][bk + 2][brow] = bq0.z; Bs[nb][bk + 3][brow] = bq0.w;
            __syncthreads();
        }
    }

    float bj[4];
#pragma unroll
    for (int j = 0; j < 4; j++) bj[j] = bias[bn + tc + j];
#pragma unroll
    for (int i = 0; i < 8; i++) {
        float* Cp = C + (size_t)(bm + tr + i) * N + bn + tc;
        float vv[4];
#pragma unroll
        for (int j = 0; j < 4; j++) {
            float m = __fadd_rn(ksum[i][j], bj[j]);
            if (SIGMOID) {
                m = fminf(5.f, fmaxf(-5.f, m));
                m = (float)(1.0 / (1.0 + exp(-(double)m)));
            }
            vv[j] = m;
        }
        *(float4*)Cp = make_float4(vv[0], vv[1], vv[2], vv[3]);
    }
}

// ---------------- LN of padded int input -> X0 ------------------------------
__global__ void __launch_bounds__(256)
ln_input_kernel(const int* __restrict__ ids,
                const float* __restrict__ gam,
                const float* __restrict__ bet,
                float* __restrict__ out)
{
    constexpr int NE = 8;   // 2048 / 256
    __shared__ double sw[8];
    __shared__ double sbc;
    const int r = blockIdx.x, tid = threadIdx.x;
    float v[NE];
#pragma unroll
    for (int i = 0; i < NE; i++) {
        const int j = tid + (i << 8);
        v[i] = (j < Ssz) ? (float)ids[(size_t)r * Ssz + j] : 0.f;
    }
    double p = 0.0;
#pragma unroll
    for (int i = 0; i < NE; i++) p += (double)v[i];
    double ws = warp_rsum_d(p);
    if ((tid & 31) == 0) sw[tid >> 5] = ws;
    __syncthreads();
    if (tid == 0) { double t = 0; for (int i = 0; i < 8; i++) t += sw[i]; sbc = t; }
    __syncthreads();
    const double mean = sbc / (double)Lsz;
    const float  mf   = (float)mean;
    double vv = 0.0;
#pragma unroll
    for (int i = 0; i < NE; i++) { double d = (double)v[i] - mean; vv += d * d; }
    ws = warp_rsum_d(vv);
    __syncthreads();
    if ((tid & 31) == 0) sw[tid >> 5] = ws;
    __syncthreads();
    if (tid == 0) { double t = 0; for (int i = 0; i < 8; i++) t += sw[i]; sbc = t; }
    __syncthreads();
    const float vf  = (float)(sbc / (double)Lsz);
    const float arg = __fadd_rn(vf, 1e-5f);
    const float rs  = (float)(1.0 / sqrt((double)arg));
#pragma unroll
    for (int i = 0; i < NE; i++) {
        const int j = tid + (i << 8);
        float t = __fmul_rn(__fmul_rn(__fsub_rn(v[i], mf), rs), gam[j]);
        out[(size_t)r * Lsz + j] = __fadd_rn(t, bet[j]);
    }
}

// ---------------- LN + exact GELU (+ optional residual), per row ------------
template<int NE>
__global__ void __launch_bounds__(256)
ln_gelu_kernel(const float* __restrict__ in,
               const float* __restrict__ gam,
               const float* __restrict__ bet,
               const float* __restrict__ res,
               float* __restrict__ out)
{
    constexpr int n = NE * 256;
    __shared__ double sw[8];
    __shared__ double sbc;
    const int r = blockIdx.x, tid = threadIdx.x;
    float v[NE];
#pragma unroll
    for (int i = 0; i < NE; i++) v[i] = in[(size_t)r * n + tid + (i << 8)];
    double p = 0.0;
#pragma unroll
    for (int i = 0; i < NE; i++) p += (double)v[i];
    double ws = warp_rsum_d(p);
    if ((tid & 31) == 0) sw[tid >> 5] = ws;
    __syncthreads();
    if (tid == 0) { double t = 0; for (int i = 0; i < 8; i++) t += sw[i]; sbc = t; }
    __syncthreads();
    const double mean = sbc / (double)n;
    const float  mf   = (float)mean;
    double vv = 0.0;
#pragma unroll
    for (int i = 0; i < NE; i++) { double d = (double)v[i] - mean; vv += d * d; }
    ws = warp_rsum_d(vv);
    __syncthreads();
    if ((tid & 31) == 0) sw[tid >> 5] = ws;
    __syncthreads();
    if (tid == 0) { double t = 0; for (int i = 0; i < 8; i++) t += sw[i]; sbc = t; }
    __syncthreads();
    const float vf  = (float)(sbc / (double)n);
    const float arg = __fadd_rn(vf, 1e-5f);
    const float rs  = (float)(1.0 / sqrt((double)arg));
#pragma unroll
    for (int i = 0; i < NE; i++) {
        const int j = tid + (i << 8);
        float x = __fadd_rn(__fmul_rn(__fmul_rn(__fsub_rn(v[i], mf), rs), gam[j]), bet[j]);
        float u = __fmul_rn(x, 0.70710678118654752f);
        float e = erff(u);
        float ge = __fmul_rn(__fmul_rn(x, __fadd_rn(e, 1.f)), 0.5f);
        float o = res ? __fadd_rn(ge, res[(size_t)r * n + j]) : ge;
        out[(size_t)r * n + j] = o;
    }
}

// ---------------- column stats ----------------------------------------------
__global__ void colstats_kernel(const float* __restrict__ Z)
{
    const int j  = blockIdx.x * 256 + threadIdx.x;
    const int ch = blockIdx.y;
    const int r0 = ch * (Bsz / CCH);
    const bool hasN = (j < Lsz - 1);
    double s1 = 0, s2 = 0, s3 = 0;
    for (int r = r0; r < r0 + (Bsz / CCH); ++r) {
        float z  = Z[(size_t)r * Lsz + j];
        float zn = hasN ? Z[(size_t)r * Lsz + j + 1] : 0.f;
        s1 += (double)z;
        s2 += (double)z * (double)z;
        s3 += (double)z * (double)zn;
    }
    g_p1[ch * Lsz + j] = s1;
    g_p2[ch * Lsz + j] = s2;
    g_p3[ch * Lsz + j] = s3;
}

__global__ void colcombine_kernel()
{
    const int j = blockIdx.x * 256 + threadIdx.x;
    double s1 = 0, s2 = 0, s3 = 0;
    for (int c = 0; c < CCH; c++) {
        s1 += g_p1[c * Lsz + j];
        s2 += g_p2[c * Lsz + j];
        s3 += g_p3[c * Lsz + j];
    }
    g_S1[j] = s1; g_S2[j] = s2; g_S3[j] = s3;
}

// ---------------- adj (corr>0.5) + consistency term -------------------------
__global__ void adjcons_kernel(const float* __restrict__ fe)
{
    __shared__ double red[256];
    const int tid = threadIdx.x;
    double cons = 0.0;
    for (int j = tid; j < Lsz; j += 256) {
        double m = g_S1[j] / (double)Bsz;
        cons += fabs(m - (double)fe[j]);
        if (j < Lsz - 1) {
            double cov = g_S3[j] - g_S1[j] * g_S1[j + 1] / (double)Bsz;
            double v1  = g_S2[j]     - g_S1[j]     * g_S1[j]     / (double)Bsz;
            double v2  = g_S2[j + 1] - g_S1[j + 1] * g_S1[j + 1] / (double)Bsz;
            double den = v1 * v2;
            float a = 0.f;
            if (den > 0.0 && cov / sqrt(den) > 0.5) a = 1.f;
            g_adj[j] = a;
        }
    }
    red[tid] = cons; __syncthreads();
    for (int o = 128; o > 0; o >>= 1) { if (tid < o) red[tid] += red[tid + o]; __syncthreads(); }
    if (tid == 0) g_cons[0] = red[0];
}

// ---------------- per-row mask / top-k / outputs -----------------------------
__global__ void __launch_bounds__(256)
rowmask_kernel(const float* __restrict__ Z, const int* __restrict__ ids,
               float* __restrict__ outG, float* __restrict__ outZ)
{
    __shared__ float zs[Lsz];
    __shared__ float sf[8], sf2[8];
    __shared__ int   si[8];
    __shared__ unsigned int hist[256];
    __shared__ unsigned int sh_prefix;
    __shared__ int sh_k;
    __shared__ int stotal;
    __shared__ int sbcast;
    __shared__ int wscan[8];

    const int r = blockIdx.x, tid = threadIdx.x;
    const int lane = tid & 31, wid = tid >> 5;
    for (int j = tid; j < Lsz; j += 256) zs[j] = Z[(size_t)r * Lsz + j];
    __syncthreads();

    // phase 1
    float ent = 0.f, dif = 0.f;
    int cnt = 0;
    for (int j = tid; j < Lsz; j += 256) {
        float p = zs[j];
        ent += -(p * logf(__fadd_rn(p, 1e-7f)) +
                 (1.f - p) * logf(__fadd_rn(__fsub_rn(1.f, p), 1e-7f)));
        if (j < Lsz - 1) dif += fabsf(__fsub_rn(zs[j + 1], zs[j])) * g_adj[j];
        if (j < Ssz) {
            int tok = ids[(size_t)r * Ssz + j];
            if (p < 0.5f && tok != 0) cnt++;
        }
    }
#pragma unroll
    for (int o = 16; o > 0; o >>= 1) {
        ent += __shfl_down_sync(0xffffffffu, ent, o);
        dif += __shfl_down_sync(0xffffffffu, dif, o);
        cnt += __shfl_down_sync(0xffffffffu, cnt, o);
    }
    if (lane == 0) { sf[wid] = ent; sf2[wid] = dif; si[wid] = cnt; }
    __syncthreads();
    if (tid == 0) {
        float e = 0.f, d = 0.f; int c = 0;
        for (int i = 0; i < 8; i++) { e += sf[i]; d += sf2[i]; c += si[i]; }
        g_rowEnt[r] = e; g_rowDiff[r] = d; stotal = c;
    }
    __syncthreads();
    const bool needfix = stotal > NEEDFIX_THRESH;

    unsigned int tsel = 0;
    int nEqKeep = 0;
    if (needfix) {
        unsigned int prefix = 0, highmask = 0;
        int k = MINTOK;
        for (int pass = 0; pass < 4; pass++) {
            const int shift = 24 - 8 * pass;
            hist[tid] = 0;
            __syncthreads();
            for (int j = tid; j < Ssz; j += 256) {
                unsigned int key = __float_as_uint(zs[j]);
                if ((key & highmask) == prefix)
                    atomicAdd(&hist[(key >> shift) & 0xFFu], 1u);
            }
            __syncthreads();
            if (tid == 0) {
                int cum = 0, b = 255;
                for (; b >= 0; --b) { cum += (int)hist[b]; if (cum >= k) break; }
                sh_k = k - (cum - (int)hist[b]);
                sh_prefix = prefix | ((unsigned int)b << shift);
            }
            __syncthreads();
            prefix = sh_prefix;
            k = sh_k;
            highmask |= 0xFFu << shift;
            __syncthreads();
        }
        tsel = prefix;
        int cg = 0;
        for (int j = tid; j < Ssz; j += 256)
            if (__float_as_uint(zs[j]) > tsel) cg++;
#pragma unroll
        for (int o = 16; o > 0; o >>= 1) cg += __shfl_down_sync(0xffffffffu, cg, o);
        if (lane == 0) si[wid] = cg;
        __syncthreads();
        if (tid == 0) { int t = 0; for (int i = 0; i < 8; i++) t += si[i]; sbcast = t; }
        __syncthreads();
        nEqKeep = MINTOK - sbcast;   // ties kept lowest-index-first
    }

    // phase 2: thread owns indices [6*tid, 6*tid+6)
    const int jbase = tid * 6;
    float zv[6]; int tok[6];
#pragma unroll
    for (int q = 0; q < 6; q++) {
        zv[q]  = zs[jbase + q];
        tok[q] = ids[(size_t)r * Ssz + jbase + q];
    }
    int eqloc[6];
    int excl = 0;
    if (needfix) {
        int myeq = 0;
#pragma unroll
        for (int q = 0; q < 6; q++) {
            const int eq = (__float_as_uint(zv[q]) == tsel) ? 1 : 0;
            eqloc[q] = myeq;
            myeq += eq;
        }
        int inc = myeq;
#pragma unroll
        for (int o = 1; o < 32; o <<= 1) {
            int t2 = __shfl_up_sync(0xffffffffu, inc, o);
            if (lane >= o) inc += t2;
        }
        excl = inc - myeq;
        if (lane == 31) wscan[wid] = inc;
        __syncthreads();
        if (tid == 0) {
            int run = 0;
            for (int i = 0; i < 8; i++) { int t3 = wscan[i]; wscan[i] = run; run += t3; }
        }
        __syncthreads();
        excl += wscan[wid];
    }
#pragma unroll
    for (int q = 0; q < 6; q++) {
        const int j = jbase + q;
        bool m = (zv[q] < 0.5f) && (tok[q] != 0);
        if (needfix) {
            const unsigned int key = __float_as_uint(zv[q]);
            const bool eq = (key == tsel);
            const bool keep = (key > tsel) || (eq && (excl + eqloc[q]) < nEqKeep);
            if (keep) m = false;
        }
        if (j == 0) m = false;   // applied after keep-adjust, as in reference
        outG[(size_t)r * Ssz + j] = m ? 0.f : (float)tok[q];
        outZ[(size_t)r * Ssz + j] = zv[q];
    }
}

// ---------------- final loss scalar -----------------------------------------
__global__ void finalize_kernel(float* __restrict__ out)
{
    __shared__ double red[256];
    const int tid = threadIdx.x;
    double e = 0, d = 0;
    for (int r = tid; r < Bsz; r += 256) {
        e += (double)g_rowEnt[r];
        d += (double)g_rowDiff[r];
    }
    red[tid] = e; __syncthreads();
    for (int o = 128; o > 0; o >>= 1) { if (tid < o) red[tid] += red[tid + o]; __syncthreads(); }
    const double entSum = red[0];
    __syncthreads();
    red[tid] = d; __syncthreads();
    for (int o = 128; o > 0; o >>= 1) { if (tid < o) red[tid] += red[tid + o]; __syncthreads(); }
    const double difSum = red[0];
    if (tid == 0) {
        double R1 = -0.001 * entSum / ((double)Bsz * (double)Lsz);
        double R2 =  0.001 * difSum / ((double)Bsz * (double)(Lsz - 1));
        double cons = 0.001 * g_cons[0] / (double)Lsz;
        out[(size_t)Bsz * Ssz] = (float)(R1 + R2 + cons);
    }
}

// ---------------- launch ------------------------------------------------------
extern "C" void kernel_launch(void* const* d_in, const int* in_sizes, int n_in,
                              void* d_out, int out_size)
{
    const float* in_g  = (const float*)d_in[0];
    const float* in_b  = (const float*)d_in[1];
    const float* wv    = (const float*)d_in[2];
    const float* bv    = (const float*)d_in[3];
    const float* wo    = (const float*)d_in[4];
    const float* bo    = (const float*)d_in[5];
    const float* w2    = (const float*)d_in[6];
    const float* b2    = (const float*)d_in[7];
    const float* g1    = (const float*)d_in[8];
    const float* be1   = (const float*)d_in[9];
    const float* w4    = (const float*)d_in[10];
    const float* b4    = (const float*)d_in[11];
    const float* g3    = (const float*)d_in[12];
    const float* be3   = (const float*)d_in[13];
    const float* w5    = (const float*)d_in[14];
    const float* b5    = (const float*)d_in[15];
    const float* g4    = (const float*)d_in[16];
    const float* be4   = (const float*)d_in[17];
    const float* w6    = (const float*)d_in[18];
    const float* b6    = (const float*)d_in[19];
    const float* g5    = (const float*)d_in[20];
    const float* be5   = (const float*)d_in[21];
    const float* w7    = (const float*)d_in[22];
    const float* b7    = (const float*)d_in[23];
    const float* g6    = (const float*)d_in[24];
    const float* be6   = (const float*)d_in[25];
    const float* wout  = (const float*)d_in[26];
    const float* bout  = (const float*)d_in[27];
    const float* fe    = (const float*)d_in[28];
    const int*   ids   = (const int*)d_in[29];
    float* out = (float*)d_out;

    float *pA, *pBf, *pC1, *pC2, *pC3, *pD1, *pD2;
    cudaGetSymbolAddress((void**)&pA,  g_A);
    cudaGetSymbolAddress((void**)&pBf, g_Bf);
    cudaGetSymbolAddress((void**)&pC1, g_C1);
    cudaGetSymbolAddress((void**)&pC2, g_C2);
    cudaGetSymbolAddress((void**)&pC3, g_C3);
    cudaGetSymbolAddress((void**)&pD1, g_D1);
    cudaGetSymbolAddress((void**)&pD2, g_D2);

    ln_input_kernel<<<Bsz, 256>>>(ids, in_g, in_b, pA);

    sgemm_nt<0><<<dim3(Lsz/64, Bsz/128), 256>>>(pA,  wv, bv, pBf, Bsz, Lsz, Lsz);
    sgemm_nt<0><<<dim3(Lsz/64, Bsz/128), 256>>>(pBf, wo, bo, pA,  Bsz, Lsz, Lsz);

    sgemm_nt<0><<<dim3(Hsz/64, Bsz/128), 256>>>(pA, w2, b2, pC1, Bsz, Hsz, Lsz);
    ln_gelu_kernel<4><<<Bsz, 256>>>(pC1, g1, be1, pC1, pC2);

    sgemm_nt<0><<<dim3(Hsz/64, Bsz/128), 256>>>(pC2, w4, b4, pC3, Bsz, Hsz, Hsz);
    ln_gelu_kernel<4><<<Bsz, 256>>>(pC3, g3, be3, nullptr, pC3);

    sgemm_nt<0><<<dim3(Hsz/64, Bsz/128), 256>>>(pC3, w5, b5, pC1, Bsz, Hsz, Hsz);
    ln_gelu_kernel<4><<<Bsz, 256>>>(pC1, g4, be4, pC2, pC1);

    sgemm_nt<0><<<dim3((Hsz/2)/64, Bsz/128), 256>>>(pC1, w6, b6, pD1, Bsz, Hsz/2, Hsz);
    ln_gelu_kernel<2><<<Bsz, 256>>>(pD1, g5, be5, nullptr, pD1);

    sgemm_nt<0><<<dim3((Hsz/4)/64, Bsz/128), 256>>>(pD1, w7, b7, pD2, Bsz, Hsz/4, Hsz/2);
    ln_gelu_kernel<1><<<Bsz, 256>>>(pD2, g6, be6, nullptr, pD2);

    // mu -> z fused into the last GEMM epilogue (identical op sequence)
    sgemm_nt<1><<<dim3(Lsz/64, Bsz/128), 256>>>(pD2, wout, bout, pA, Bsz, Lsz, Hsz/4);

    colstats_kernel<<<dim3(Lsz/256, CCH), 256>>>(pA);
    colcombine_kernel<<<Lsz/256, 256>>>();
    adjcons_kernel<<<1, 256>>>(fe);

    rowmask_kernel<<<Bsz, 256>>>(pA, ids, out, out + (size_t)Bsz * Ssz + 1);

    finalize_kernel<<<1, 256>>>(out);
}

// round 15
// speedup vs baseline: 1.6369x; 1.6369x over previous
#include <cuda_runtime.h>
#include <cuda_bf16.h>
#include <math.h>

// Problem constants
#define Bsz 4096
#define Ssz 1536
#define Lsz 2048
#define Hsz 1024
#define MINTOK 460                     // int(0.3*1536)
#define NEEDFIX_THRESH (Ssz - MINTOK)  // 1076

// ---------------- scratch (device globals; no allocations allowed) ----------
__device__ float g_A [(size_t)Bsz * Lsz];
__device__ float g_Bf[(size_t)Bsz * Lsz];
__device__ float g_C1[(size_t)Bsz * Hsz];
__device__ float g_C2[(size_t)Bsz * Hsz];
__device__ float g_C3[(size_t)Bsz * Hsz];
__device__ float g_D1[(size_t)Bsz * (Hsz/2)];
__device__ float g_D2[(size_t)Bsz * (Hsz/4)];

#define CCH 64
__device__ double g_p1[CCH * Lsz];
__device__ double g_p2[CCH * Lsz];
__device__ double g_p3[CCH * Lsz];
__device__ double g_S1[Lsz], g_S2[Lsz], g_S3[Lsz];
__device__ float  g_adj[Lsz];
__device__ float  g_rowEnt[Bsz], g_rowDiff[Bsz];
__device__ double g_cons[1];

// ---- f32x2 packed helpers (PTX-only; each half is an independent IEEE op) --
__device__ __forceinline__ unsigned long long pk2(float lo, float hi) {
    unsigned long long r;
    asm("mov.b64 %0, {%1, %2};" : "=l"(r) : "f"(lo), "f"(hi));
    return r;
}
__device__ __forceinline__ void upk2(unsigned long long v, float& lo, float& hi) {
    asm("mov.b64 {%0, %1}, %2;" : "=f"(lo), "=f"(hi) : "l"(v));
}
__device__ __forceinline__ unsigned long long fma2(unsigned long long a,
                                                   unsigned long long b,
                                                   unsigned long long c) {
    unsigned long long d;
    asm("fma.rn.f32x2 %0, %1, %2, %3;" : "=l"(d) : "l"(a), "l"(b), "l"(c));
    return d;
}

union F4U2 { float4 f; struct { unsigned long long lo, hi; } u; };

__device__ __forceinline__ double warp_rsum_d(double x) {
#pragma unroll
    for (int o = 16; o > 0; o >>= 1)
        x += __shfl_down_sync(0xffffffffu, x, o);
    return x;
}

// ---------------- GEMM: C[M,N] = A[M,K] @ W[N,K]^T + bias[N] ----------------
// Numerics (frozen, = round 13): per output, fp32 FFMA over each ascending
// 64-k chunk; chunk sums folded ascending into an fp32 accumulator;
// (ksum)+bias at the end. f32x2 packs two M-adjacent outputs per instruction.
// SIGMOID==1 applies clip(-5,5) + exact double sigmoid in the epilogue
// (identical op sequence to the old standalone kernel).
// Mainloop structure is round-13 VERBATIM: TWO __syncthreads per stage.
// (Round 14 measured that removing the pre-staging barrier interleaves STS
// with other warps' LDS and slows the kernel 60% — keep both barriers.)
template<int SIGMOID>
__global__ void __launch_bounds__(256, 2)
sgemm_nt(const float* __restrict__ A, const float* __restrict__ W,
         const float* __restrict__ bias, float* __restrict__ C,
         int M, int N, int K)
{
    constexpr int BK = 16;
    __shared__ float As[2][BK][128];
    __shared__ float Bs[2][BK][64 + 4];
    const int tid = threadIdx.x;
    const int bm = blockIdx.y * 128;
    const int bn = blockIdx.x * 64;
    const int tr = (tid >> 4) << 3;     // 0..120 step 8
    const int tc = (tid & 15) << 2;     // 0..60 step 4

    const int arow = tid & 127;
    const int ak   = (tid >> 7) << 3;   // 0 or 8
    const int brow = tid & 63;
    const int bk   = (tid >> 6) << 2;   // 0,4,8,12

    const float* Ap = A + (size_t)(bm + arow) * K + ak;
    const float* Wp = W + (size_t)(bn + brow) * K + bk;

    unsigned long long facc2[4][4];
    float ksum[8][4];
#pragma unroll
    for (int i = 0; i < 8; i++)
#pragma unroll
        for (int j = 0; j < 4; j++) ksum[i][j] = 0.f;
#pragma unroll
    for (int p = 0; p < 4; p++)
#pragma unroll
        for (int j = 0; j < 4; j++) facc2[p][j] = 0ull;

    const int nch = K / BK;   // 16-k stages; fold every 4 stages (64 k)

    float4 aq0 = *(const float4*)(Ap);
    float4 aq1 = *(const float4*)(Ap + 4);
    float4 bq0 = *(const float4*)(Wp);
    As[0][ak + 0][arow] = aq0.x; As[0][ak + 1][arow] = aq0.y;
    As[0][ak + 2][arow] = aq0.z; As[0][ak + 3][arow] = aq0.w;
    As[0][ak + 4][arow] = aq1.x; As[0][ak + 5][arow] = aq1.y;
    As[0][ak + 6][arow] = aq1.z; As[0][ak + 7][arow] = aq1.w;
    Bs[0][bk + 0][brow] = bq0.x; Bs[0][bk + 1][brow] = bq0.y;
    Bs[0][bk + 2][brow] = bq0.z; Bs[0][bk + 3][brow] = bq0.w;
    __syncthreads();

    for (int c = 0; c < nch; c++) {
        const int buf = c & 1;
        const bool more = (c + 1 < nch);
        if (more) {
            const int k0 = (c + 1) * BK;
            aq0 = *(const float4*)(Ap + k0);
            aq1 = *(const float4*)(Ap + k0 + 4);
            bq0 = *(const float4*)(Wp + k0);
        }

#pragma unroll
        for (int k = 0; k < BK; k++) {
            F4U2 a0, a1;
            a0.f = *(const float4*)(&As[buf][k][tr]);
            a1.f = *(const float4*)(&As[buf][k][tr + 4]);
            const float4 bv = *(const float4*)(&Bs[buf][k][tc]);
            const unsigned long long bb0 = pk2(bv.x, bv.x);
            const unsigned long long bb1 = pk2(bv.y, bv.y);
            const unsigned long long bb2 = pk2(bv.z, bv.z);
            const unsigned long long bb3 = pk2(bv.w, bv.w);
            facc2[0][0] = fma2(a0.u.lo, bb0, facc2[0][0]);
            facc2[0][1] = fma2(a0.u.lo, bb1, facc2[0][1]);
            facc2[0][2] = fma2(a0.u.lo, bb2, facc2[0][2]);
            facc2[0][3] = fma2(a0.u.lo, bb3, facc2[0][3]);
            facc2[1][0] = fma2(a0.u.hi, bb0, facc2[1][0]);
            facc2[1][1] = fma2(a0.u.hi, bb1, facc2[1][1]);
            facc2[1][2] = fma2(a0.u.hi, bb2, facc2[1][2]);
            facc2[1][3] = fma2(a0.u.hi, bb3, facc2[1][3]);
            facc2[2][0] = fma2(a1.u.lo, bb0, facc2[2][0]);
            facc2[2][1] = fma2(a1.u.lo, bb1, facc2[2][1]);
            facc2[2][2] = fma2(a1.u.lo, bb2, facc2[2][2]);
            facc2[2][3] = fma2(a1.u.lo, bb3, facc2[2][3]);
            facc2[3][0] = fma2(a1.u.hi, bb0, facc2[3][0]);
            facc2[3][1] = fma2(a1.u.hi, bb1, facc2[3][1]);
            facc2[3][2] = fma2(a1.u.hi, bb2, facc2[3][2]);
            facc2[3][3] = fma2(a1.u.hi, bb3, facc2[3][3]);
        }

        if ((c & 3) == 3) {
            // plain fp32 fold of the completed 64-k chunk (ascending chunks)
#pragma unroll
            for (int p = 0; p < 4; p++)
#pragma unroll
                for (int j = 0; j < 4; j++) {
                    float flo, fhi;
                    upk2(facc2[p][j], flo, fhi);
                    ksum[2 * p][j]     = __fadd_rn(ksum[2 * p][j], flo);
                    ksum[2 * p + 1][j] = __fadd_rn(ksum[2 * p + 1][j], fhi);
                    facc2[p][j] = 0ull;
                }
        }

        if (more) {
            __syncthreads();
            const int nb = buf ^ 1;
            As[nb][ak + 0][arow] = aq0.x; As[nb][ak + 1][arow] = aq0.y;
            As[nb][ak + 2][arow] = aq0.z; As[nb][ak + 3][arow] = aq0.w;
            As[nb][ak + 4][arow] = aq1.x; As[nb][ak + 5][arow] = aq1.y;
            As[nb][ak + 6][arow] = aq1.z; As[nb][ak + 7][arow] = aq1.w;
            Bs[nb][bk + 0][brow] = bq0.x; Bs[nb][bk + 1][brow] = bq0.y;
            Bs[nb][bk + 2][brow] = bq0.z; Bs[nb][bk + 3][brow] = bq0.w;
            __syncthreads();
        }
    }

    float bj[4];
#pragma unroll
    for (int j = 0; j < 4; j++) bj[j] = bias[bn + tc + j];
#pragma unroll
    for (int i = 0; i < 8; i++) {
        float* Cp = C + (size_t)(bm + tr + i) * N + bn + tc;
        float vv[4];
#pragma unroll
        for (int j = 0; j < 4; j++) {
            float m = __fadd_rn(ksum[i][j], bj[j]);
            if (SIGMOID) {
                m = fminf(5.f, fmaxf(-5.f, m));
                m = (float)(1.0 / (1.0 + exp(-(double)m)));
            }
            vv[j] = m;
        }
        *(float4*)Cp = make_float4(vv[0], vv[1], vv[2], vv[3]);
    }
}

// ---------------- LN of padded int input -> X0 ------------------------------
__global__ void __launch_bounds__(256)
ln_input_kernel(const int* __restrict__ ids,
                const float* __restrict__ gam,
                const float* __restrict__ bet,
                float* __restrict__ out)
{
    constexpr int NE = 8;   // 2048 / 256
    __shared__ double sw[8];
    __shared__ double sbc;
    const int r = blockIdx.x, tid = threadIdx.x;
    float v[NE];
#pragma unroll
    for (int i = 0; i < NE; i++) {
        const int j = tid + (i << 8);
        v[i] = (j < Ssz) ? (float)ids[(size_t)r * Ssz + j] : 0.f;
    }
    double p = 0.0;
#pragma unroll
    for (int i = 0; i < NE; i++) p += (double)v[i];
    double ws = warp_rsum_d(p);
    if ((tid & 31) == 0) sw[tid >> 5] = ws;
    __syncthreads();
    if (tid == 0) { double t = 0; for (int i = 0; i < 8; i++) t += sw[i]; sbc = t; }
    __syncthreads();
    const double mean = sbc / (double)Lsz;
    const float  mf   = (float)mean;
    double vv = 0.0;
#pragma unroll
    for (int i = 0; i < NE; i++) { double d = (double)v[i] - mean; vv += d * d; }
    ws = warp_rsum_d(vv);
    __syncthreads();
    if ((tid & 31) == 0) sw[tid >> 5] = ws;
    __syncthreads();
    if (tid == 0) { double t = 0; for (int i = 0; i < 8; i++) t += sw[i]; sbc = t; }
    __syncthreads();
    const float vf  = (float)(sbc / (double)Lsz);
    const float arg = __fadd_rn(vf, 1e-5f);
    const float rs  = (float)(1.0 / sqrt((double)arg));
#pragma unroll
    for (int i = 0; i < NE; i++) {
        const int j = tid + (i << 8);
        float t = __fmul_rn(__fmul_rn(__fsub_rn(v[i], mf), rs), gam[j]);
        out[(size_t)r * Lsz + j] = __fadd_rn(t, bet[j]);
    }
}

// ---------------- LN + exact GELU (+ optional residual), per row ------------
template<int NE>
__global__ void __launch_bounds__(256)
ln_gelu_kernel(const float* __restrict__ in,
               const float* __restrict__ gam,
               const float* __restrict__ bet,
               const float* __restrict__ res,
               float* __restrict__ out)
{
    constexpr int n = NE * 256;
    __shared__ double sw[8];
    __shared__ double sbc;
    const int r = blockIdx.x, tid = threadIdx.x;
    float v[NE];
#pragma unroll
    for (int i = 0; i < NE; i++) v[i] = in[(size_t)r * n + tid + (i << 8)];
    double p = 0.0;
#pragma unroll
    for (int i = 0; i < NE; i++) p += (double)v[i];
    double ws = warp_rsum_d(p);
    if ((tid & 31) == 0) sw[tid >> 5] = ws;
    __syncthreads();
    if (tid == 0) { double t = 0; for (int i = 0; i < 8; i++) t += sw[i]; sbc = t; }
    __syncthreads();
    const double mean = sbc / (double)n;
    const float  mf   = (float)mean;
    double vv = 0.0;
#pragma unroll
    for (int i = 0; i < NE; i++) { double d = (double)v[i] - mean; vv += d * d; }
    ws = warp_rsum_d(vv);
    __syncthreads();
    if ((tid & 31) == 0) sw[tid >> 5] = ws;
    __syncthreads();
    if (tid == 0) { double t = 0; for (int i = 0; i < 8; i++) t += sw[i]; sbc = t; }
    __syncthreads();
    const float vf  = (float)(sbc / (double)n);
    const float arg = __fadd_rn(vf, 1e-5f);
    const float rs  = (float)(1.0 / sqrt((double)arg));
#pragma unroll
    for (int i = 0; i < NE; i++) {
        const int j = tid + (i << 8);
        float x = __fadd_rn(__fmul_rn(__fmul_rn(__fsub_rn(v[i], mf), rs), gam[j]), bet[j]);
        float u = __fmul_rn(x, 0.70710678118654752f);
        float e = erff(u);
        float ge = __fmul_rn(__fmul_rn(x, __fadd_rn(e, 1.f)), 0.5f);
        float o = res ? __fadd_rn(ge, res[(size_t)r * n + j]) : ge;
        out[(size_t)r * n + j] = o;
    }
}

// ---------------- column stats ----------------------------------------------
__global__ void colstats_kernel(const float* __restrict__ Z)
{
    const int j  = blockIdx.x * 256 + threadIdx.x;
    const int ch = blockIdx.y;
    const int r0 = ch * (Bsz / CCH);
    const bool hasN = (j < Lsz - 1);
    double s1 = 0, s2 = 0, s3 = 0;
    for (int r = r0; r < r0 + (Bsz / CCH); ++r) {
        float z  = Z[(size_t)r * Lsz + j];
        float zn = hasN ? Z[(size_t)r * Lsz + j + 1] : 0.f;
        s1 += (double)z;
        s2 += (double)z * (double)z;
        s3 += (double)z * (double)zn;
    }
    g_p1[ch * Lsz + j] = s1;
    g_p2[ch * Lsz + j] = s2;
    g_p3[ch * Lsz + j] = s3;
}

__global__ void colcombine_kernel()
{
    const int j = blockIdx.x * 256 + threadIdx.x;
    double s1 = 0, s2 = 0, s3 = 0;
    for (int c = 0; c < CCH; c++) {
        s1 += g_p1[c * Lsz + j];
        s2 += g_p2[c * Lsz + j];
        s3 += g_p3[c * Lsz + j];
    }
    g_S1[j] = s1; g_S2[j] = s2; g_S3[j] = s3;
}

// ---------------- adj (corr>0.5) + consistency term -------------------------
__global__ void adjcons_kernel(const float* __restrict__ fe)
{
    __shared__ double red[256];
    const int tid = threadIdx.x;
    double cons = 0.0;
    for (int j = tid; j < Lsz; j += 256) {
        double m = g_S1[j] / (double)Bsz;
        cons += fabs(m - (double)fe[j]);
        if (j < Lsz - 1) {
            double cov = g_S3[j] - g_S1[j] * g_S1[j + 1] / (double)Bsz;
            double v1  = g_S2[j]     - g_S1[j]     * g_S1[j]     / (double)Bsz;
            double v2  = g_S2[j + 1] - g_S1[j + 1] * g_S1[j + 1] / (double)Bsz;
            double den = v1 * v2;
            float a = 0.f;
            if (den > 0.0 && cov / sqrt(den) > 0.5) a = 1.f;
            g_adj[j] = a;
        }
    }
    red[tid] = cons; __syncthreads();
    for (int o = 128; o > 0; o >>= 1) { if (tid < o) red[tid] += red[tid + o]; __syncthreads(); }
    if (tid == 0) g_cons[0] = red[0];
}

// ---------------- per-row mask / top-k / outputs -----------------------------
__global__ void __launch_bounds__(256)
rowmask_kernel(const float* __restrict__ Z, const int* __restrict__ ids,
               float* __restrict__ outG, float* __restrict__ outZ)
{
    __shared__ float zs[Lsz];
    __shared__ float sf[8], sf2[8];
    __shared__ int   si[8];
    __shared__ unsigned int hist[256];
    __shared__ unsigned int sh_prefix;
    __shared__ int sh_k;
    __shared__ int stotal;
    __shared__ int sbcast;
    __shared__ int wscan[8];

    const int r = blockIdx.x, tid = threadIdx.x;
    const int lane = tid & 31, wid = tid >> 5;
    for (int j = tid; j < Lsz; j += 256) zs[j] = Z[(size_t)r * Lsz + j];
    __syncthreads();

    // phase 1
    float ent = 0.f, dif = 0.f;
    int cnt = 0;
    for (int j = tid; j < Lsz; j += 256) {
        float p = zs[j];
        ent += -(p * logf(__fadd_rn(p, 1e-7f)) +
                 (1.f - p) * logf(__fadd_rn(__fsub_rn(1.f, p), 1e-7f)));
        if (j < Lsz - 1) dif += fabsf(__fsub_rn(zs[j + 1], zs[j])) * g_adj[j];
        if (j < Ssz) {
            int tok = ids[(size_t)r * Ssz + j];
            if (p < 0.5f && tok != 0) cnt++;
        }
    }
#pragma unroll
    for (int o = 16; o > 0; o >>= 1) {
        ent += __shfl_down_sync(0xffffffffu, ent, o);
        dif += __shfl_down_sync(0xffffffffu, dif, o);
        cnt += __shfl_down_sync(0xffffffffu, cnt, o);
    }
    if (lane == 0) { sf[wid] = ent; sf2[wid] = dif; si[wid] = cnt; }
    __syncthreads();
    if (tid == 0) {
        float e = 0.f, d = 0.f; int c = 0;
        for (int i = 0; i < 8; i++) { e += sf[i]; d += sf2[i]; c += si[i]; }
        g_rowEnt[r] = e; g_rowDiff[r] = d; stotal = c;
    }
    __syncthreads();
    const bool needfix = stotal > NEEDFIX_THRESH;

    unsigned int tsel = 0;
    int nEqKeep = 0;
    if (needfix) {
        unsigned int prefix = 0, highmask = 0;
        int k = MINTOK;
        for (int pass = 0; pass < 4; pass++) {
            const int shift = 24 - 8 * pass;
            hist[tid] = 0;
            __syncthreads();
            for (int j = tid; j < Ssz; j += 256) {
                unsigned int key = __float_as_uint(zs[j]);
                if ((key & highmask) == prefix)
                    atomicAdd(&hist[(key >> shift) & 0xFFu], 1u);
            }
            __syncthreads();
            if (tid == 0) {
                int cum = 0, b = 255;
                for (; b >= 0; --b) { cum += (int)hist[b]; if (cum >= k) break; }
                sh_k = k - (cum - (int)hist[b]);
                sh_prefix = prefix | ((unsigned int)b << shift);
            }
            __syncthreads();
            prefix = sh_prefix;
            k = sh_k;
            highmask |= 0xFFu << shift;
            __syncthreads();
        }
        tsel = prefix;
        int cg = 0;
        for (int j = tid; j < Ssz; j += 256)
            if (__float_as_uint(zs[j]) > tsel) cg++;
#pragma unroll
        for (int o = 16; o > 0; o >>= 1) cg += __shfl_down_sync(0xffffffffu, cg, o);
        if (lane == 0) si[wid] = cg;
        __syncthreads();
        if (tid == 0) { int t = 0; for (int i = 0; i < 8; i++) t += si[i]; sbcast = t; }
        __syncthreads();
        nEqKeep = MINTOK - sbcast;   // ties kept lowest-index-first
    }

    // phase 2: thread owns indices [6*tid, 6*tid+6)
    const int jbase = tid * 6;
    float zv[6]; int tok[6];
#pragma unroll
    for (int q = 0; q < 6; q++) {
        zv[q]  = zs[jbase + q];
        tok[q] = ids[(size_t)r * Ssz + jbase + q];
    }
    int eqloc[6];
    int excl = 0;
    if (needfix) {
        int myeq = 0;
#pragma unroll
        for (int q = 0; q < 6; q++) {
            const int eq = (__float_as_uint(zv[q]) == tsel) ? 1 : 0;
            eqloc[q] = myeq;
            myeq += eq;
        }
        int inc = myeq;
#pragma unroll
        for (int o = 1; o < 32; o <<= 1) {
            int t2 = __shfl_up_sync(0xffffffffu, inc, o);
            if (lane >= o) inc += t2;
        }
        excl = inc - myeq;
        if (lane == 31) wscan[wid] = inc;
        __syncthreads();
        if (tid == 0) {
            int run = 0;
            for (int i = 0; i < 8; i++) { int t3 = wscan[i]; wscan[i] = run; run += t3; }
        }
        __syncthreads();
        excl += wscan[wid];
    }
#pragma unroll
    for (int q = 0; q < 6; q++) {
        const int j = jbase + q;
        bool m = (zv[q] < 0.5f) && (tok[q] != 0);
        if (needfix) {
            const unsigned int key = __float_as_uint(zv[q]);
            const bool eq = (key == tsel);
            const bool keep = (key > tsel) || (eq && (excl + eqloc[q]) < nEqKeep);
            if (keep) m = false;
        }
        if (j == 0) m = false;   // applied after keep-adjust, as in reference
        outG[(size_t)r * Ssz + j] = m ? 0.f : (float)tok[q];
        outZ[(size_t)r * Ssz + j] = zv[q];
    }
}

// ---------------- final loss scalar -----------------------------------------
__global__ void finalize_kernel(float* __restrict__ out)
{
    __shared__ double red[256];
    const int tid = threadIdx.x;
    double e = 0, d = 0;
    for (int r = tid; r < Bsz; r += 256) {
        e += (double)g_rowEnt[r];
        d += (double)g_rowDiff[r];
    }
    red[tid] = e; __syncthreads();
    for (int o = 128; o > 0; o >>= 1) { if (tid < o) red[tid] += red[tid + o]; __syncthreads(); }
    const double entSum = red[0];
    __syncthreads();
    red[tid] = d; __syncthreads();
    for (int o = 128; o > 0; o >>= 1) { if (tid < o) red[tid] += red[tid + o]; __syncthreads(); }
    const double difSum = red[0];
    if (tid == 0) {
        double R1 = -0.001 * entSum / ((double)Bsz * (double)Lsz);
        double R2 =  0.001 * difSum / ((double)Bsz * (double)(Lsz - 1));
        double cons = 0.001 * g_cons[0] / (double)Lsz;
        out[(size_t)Bsz * Ssz] = (float)(R1 + R2 + cons);
    }
}

// ---------------- launch ------------------------------------------------------
extern "C" void kernel_launch(void* const* d_in, const int* in_sizes, int n_in,
                              void* d_out, int out_size)
{
    const float* in_g  = (const float*)d_in[0];
    const float* in_b  = (const float*)d_in[1];
    const float* wv    = (const float*)d_in[2];
    const float* bv    = (const float*)d_in[3];
    const float* wo    = (const float*)d_in[4];
    const float* bo    = (const float*)d_in[5];
    const float* w2    = (const float*)d_in[6];
    const float* b2    = (const float*)d_in[7];
    const float* g1    = (const float*)d_in[8];
    const float* be1   = (const float*)d_in[9];
    const float* w4    = (const float*)d_in[10];
    const float* b4    = (const float*)d_in[11];
    const float* g3    = (const float*)d_in[12];
    const float* be3   = (const float*)d_in[13];
    const float* w5    = (const float*)d_in[14];
    const float* b5    = (const float*)d_in[15];
    const float* g4    = (const float*)d_in[16];
    const float* be4   = (const float*)d_in[17];
    const float* w6    = (const float*)d_in[18];
    const float* b6    = (const float*)d_in[19];
    const float* g5    = (const float*)d_in[20];
    const float* be5   = (const float*)d_in[21];
    const float* w7    = (const float*)d_in[22];
    const float* b7    = (const float*)d_in[23];
    const float* g6    = (const float*)d_in[24];
    const float* be6   = (const float*)d_in[25];
    const float* wout  = (const float*)d_in[26];
    const float* bout  = (const float*)d_in[27];
    const float* fe    = (const float*)d_in[28];
    const int*   ids   = (const int*)d_in[29];
    float* out = (float*)d_out;

    float *pA, *pBf, *pC1, *pC2, *pC3, *pD1, *pD2;
    cudaGetSymbolAddress((void**)&pA,  g_A);
    cudaGetSymbolAddress((void**)&pBf, g_Bf);
    cudaGetSymbolAddress((void**)&pC1, g_C1);
    cudaGetSymbolAddress((void**)&pC2, g_C2);
    cudaGetSymbolAddress((void**)&pC3, g_C3);
    cudaGetSymbolAddress((void**)&pD1, g_D1);
    cudaGetSymbolAddress((void**)&pD2, g_D2);

    ln_input_kernel<<<Bsz, 256>>>(ids, in_g, in_b, pA);

    sgemm_nt<0><<<dim3(Lsz/64, Bsz/128), 256>>>(pA,  wv, bv, pBf, Bsz, Lsz, Lsz);
    sgemm_nt<0><<<dim3(Lsz/64, Bsz/128), 256>>>(pBf, wo, bo, pA,  Bsz, Lsz, Lsz);

    sgemm_nt<0><<<dim3(Hsz/64, Bsz/128), 256>>>(pA, w2, b2, pC1, Bsz, Hsz, Lsz);
    ln_gelu_kernel<4><<<Bsz, 256>>>(pC1, g1, be1, pC1, pC2);

    sgemm_nt<0><<<dim3(Hsz/64, Bsz/128), 256>>>(pC2, w4, b4, pC3, Bsz, Hsz, Hsz);
    ln_gelu_kernel<4><<<Bsz, 256>>>(pC3, g3, be3, nullptr, pC3);

    sgemm_nt<0><<<dim3(Hsz/64, Bsz/128), 256>>>(pC3, w5, b5, pC1, Bsz, Hsz, Hsz);
    ln_gelu_kernel<4><<<Bsz, 256>>>(pC1, g4, be4, pC2, pC1);

    sgemm_nt<0><<<dim3((Hsz/2)/64, Bsz/128), 256>>>(pC1, w6, b6, pD1, Bsz, Hsz/2, Hsz);
    ln_gelu_kernel<2><<<Bsz, 256>>>(pD1, g5, be5, nullptr, pD1);

    sgemm_nt<0><<<dim3((Hsz/4)/64, Bsz/128), 256>>>(pD1, w7, b7, pD2, Bsz, Hsz/4, Hsz/2);
    ln_gelu_kernel<1><<<Bsz, 256>>>(pD2, g6, be6, nullptr, pD2);

    // mu -> z fused into the last GEMM epilogue (identical op sequence)
    sgemm_nt<1><<<dim3(Lsz/64, Bsz/128), 256>>>(pD2, wout, bout, pA, Bsz, Lsz, Hsz/4);

    colstats_kernel<<<dim3(Lsz/256, CCH), 256>>>(pA);
    colcombine_kernel<<<Lsz/256, 256>>>();
    adjcons_kernel<<<1, 256>>>(fe);

    rowmask_kernel<<<Bsz, 256>>>(pA, ids, out, out + (size_t)Bsz * Ssz + 1);

    finalize_kernel<<<1, 256>>>(out);
}